// round 1
// baseline (speedup 1.0000x reference)
#include <cuda_runtime.h>

#define BB 32
#define NN 128
#define DD 135
#define OBS 7
#define FF 64
#define ADJ_OFF 7

// ---------------- device global scratch (allocation-free) ----------------
__device__ float g_norm[BB * NN];          // post-where norm per (b, col)
__device__ float g_ee[BB * NN * FF];       // edge_emb
__device__ float g_curA[BB * NN * FF];
__device__ float g_curB[BB * NN * FF];
__device__ float g_PQ[BB * NN * 8];        // [b][i][0..3]=P, [4..7]=Q
__device__ float g_Abias[BB * 4];

// ---------------- K1: norm per column + store -----------------------------
__global__ void k_norm(const float* __restrict__ obs) {
    int b = blockIdx.x, j = threadIdx.x;
    const float* o = obs + b * (NN * DD) + ADJ_OFF + j;
    int cnt = 0;
#pragma unroll 8
    for (int i = 0; i < NN; i++) cnt += (o[i * DD] != 0.0f) ? 1 : 0;
    g_norm[b * NN + j] = (cnt == 0) ? 1.0f : (float)cnt;
}

// ---------------- K2: edge stage + init embedding --------------------------
// grid = 32 batches * 8 row-tiles (16 rows each), 256 threads
#define EDGE_SMEM_FLOATS (1024 + 512 + 512 + 64*65 + 8192 + 16*129 + 1024 + 128 + 256)
__global__ void k_edge(const float* __restrict__ obs,
                       const float* __restrict__ W_init,
                       const float* __restrict__ W_ee,
                       const float* __restrict__ W_ef) {
    extern __shared__ float sm[];
    float* s_nf   = sm;                 // 128*8
    float* s_wee  = s_nf + 1024;        // 64*8 (rows 0..62 valid, rest 0)
    float* s_wi   = s_wee + 512;        // 64*8 (cols 0..6 valid, rest 0)
    float* s_weft = s_wi + 512;         // 64*65 transposed W_ef: [k*65+f]
    float* s_c    = s_weft + 64 * 65;   // 128*64
    float* s_adj  = s_c + 8192;         // 16*129 (padded rows)
    float* s_es   = s_adj + 16 * 129;   // 16*64
    float* s_nm   = s_es + 1024;        // 128
    float* s_red  = s_nm + 128;         // 256

    int b = blockIdx.x >> 3;
    int r0 = (blockIdx.x & 7) << 4;
    int t = threadIdx.x;
    const float* ob = obs + b * NN * DD;

    // loads
    for (int idx = t; idx < NN * OBS; idx += 256) {
        int j = idx / OBS, d = idx - j * OBS;
        s_nf[j * 8 + d] = ob[j * DD + d];
    }
    for (int idx = t; idx < 512; idx += 256)
        s_wee[idx] = (idx < 63 * 8) ? W_ee[idx] : 0.0f;
    for (int idx = t; idx < 512; idx += 256) {
        int f = idx >> 3, d = idx & 7;
        s_wi[idx] = (d < 7) ? W_init[f * 7 + d] : 0.0f;
    }
    for (int idx = t; idx < 4096; idx += 256) {   // coalesced read, padded transpose store
        int f = idx >> 6, k = idx & 63;
        s_weft[k * 65 + f] = W_ef[idx];
    }
    for (int idx = t; idx < 16 * NN; idx += 256) {
        int r = idx >> 7, j = idx & 127;
        s_adj[r * 129 + j] = ob[(r0 + r) * DD + ADJ_OFF + j];
    }
    for (int idx = t; idx < NN; idx += 256) s_nm[idx] = g_norm[b * NN + idx];
    float mx = 0.0f;
    for (int idx = t; idx < BB * NN; idx += 256) mx = fmaxf(mx, g_norm[idx]);
    s_red[t] = mx;
    __syncthreads();
    for (int s = 128; s > 0; s >>= 1) {
        if (t < s) s_red[t] = fmaxf(s_red[t], s_red[t + s]);
        __syncthreads();
    }
    float maxnorm = s_red[0];

    // per-node edge constant c[j][k] = W_ee[k,1:8] . nf[j]
    for (int idx = t; idx < NN * FF; idx += 256) {
        int j = idx >> 6, k = idx & 63;
        float c = 0.0f;
        if (k < 63) {
            const float* w = s_wee + k * 8;
            const float* nf = s_nf + j * 8;
#pragma unroll
            for (int d = 0; d < 7; d++) c = fmaf(w[d + 1], nf[d], c);
        }
        s_c[idx] = c;
    }
    // init embedding for our 16 rows -> g_curA
    for (int idx = t; idx < 16 * FF; idx += 256) {
        int r = idx >> 6, f = idx & 63;
        const float* w = s_wi + f * 8;
        const float* nf = s_nf + (r0 + r) * 8;
        float e = 0.0f;
#pragma unroll
        for (int d = 0; d < 7; d++) e = fmaf(w[d], nf[d], e);
        g_curA[(b * NN + r0 + r) * FF + f] = fmaxf(e, 0.0f);
    }
    __syncthreads();

    // edge sum: thread -> (row r in 0..15, feature group g: f = 4g..4g+3)
    {
        int r = t >> 4, g = t & 15;
        int f0 = g << 2;
        float4 w0;
        w0.x = s_wee[(f0 + 0) * 8];
        w0.y = s_wee[(f0 + 1) * 8];
        w0.z = s_wee[(f0 + 2) * 8];
        w0.w = s_wee[(f0 + 3) * 8];   // f0+3==63 -> zero row (harmless, overwritten)
        float4 acc = make_float4(0.f, 0.f, 0.f, 0.f);
        const float* arow = s_adj + r * 129;
        for (int j = 0; j < NN; j++) {
            float a = arow[j];
            if (a != 0.0f) {
                float4 c = *(const float4*)(s_c + j * 64 + f0);
                acc.x += fmaxf(fmaf(a, w0.x, c.x), 0.0f);
                acc.y += fmaxf(fmaf(a, w0.y, c.y), 0.0f);
                acc.z += fmaxf(fmaf(a, w0.z, c.z), 0.0f);
                acc.w += fmaxf(fmaf(a, w0.w, c.w), 0.0f);
            }
        }
        float nrm = s_nm[r0 + r];
        float inv = 1.0f / nrm;
        float* es = s_es + r * 64 + f0;
        es[0] = acc.x * inv;
        es[1] = acc.y * inv;
        es[2] = acc.z * inv;
        es[3] = (g == 15) ? (nrm / maxnorm) : acc.w * inv;  // slot 63 = norm feature
    }
    __syncthreads();

    // edge_emb = relu(es @ W_ef^T)   (64-dot incl. norm feature at k=63)
    for (int idx = t; idx < 16 * FF; idx += 256) {
        int r = idx >> 6, f = idx & 63;
        const float* e = s_es + r * 64;
        float acc = 0.0f;
#pragma unroll 16
        for (int k = 0; k < 64; k++) acc = fmaf(s_weft[k * 65 + f], e[k], acc);
        g_ee[(b * NN + r0 + r) * FF + f] = fmaxf(acc, 0.0f);
    }
}

// ---------------- K3: one MPNN layer ---------------------------------------
// grid = 32 batches * 16 row-tiles (8 rows each), 256 threads
#define LAYER_SMEM_FLOATS (8192 + 8*129 + 128*65 + 512 + 512 + 512 + 8)
__global__ void k_layer(const float* __restrict__ obs,
                        const float* __restrict__ Wm,
                        const float* __restrict__ Wu,
                        int flip) {
    extern __shared__ float sm[];
    float* s_cur = sm;                  // 128*64 (whole batch cur)
    float* s_adj = s_cur + 8192;        // 8*129
    float* s_w   = s_adj + 8 * 129;     // 128*65 transposed weights [k*65+f]
    float* s_ee  = s_w + 128 * 65;      // 8*64
    float* s_agg = s_ee + 512;          // 8*64
    float* s_msg = s_agg + 512;         // 8*64
    float* s_nm  = s_msg + 512;         // 8

    const float* g_in = flip ? g_curB : g_curA;
    float* g_out = flip ? g_curA : g_curB;

    int b = blockIdx.x >> 4;
    int r0 = (blockIdx.x & 15) << 3;
    int t = threadIdx.x;
    const float* ob = obs + b * NN * DD;

    for (int idx = t; idx < 8192; idx += 256) s_cur[idx] = g_in[b * 8192 + idx];
    for (int idx = t; idx < 8 * NN; idx += 256) {
        int r = idx >> 7, j = idx & 127;
        s_adj[r * 129 + j] = ob[(r0 + r) * DD + ADJ_OFF + j];
    }
    for (int idx = t; idx < 512; idx += 256) s_ee[idx] = g_ee[(b * NN + r0) * FF + idx];
    if (t < 8) s_nm[t] = g_norm[b * NN + r0 + t];
    for (int idx = t; idx < 8192; idx += 256) {   // W_msg transposed into s_w
        int f = idx >> 7, k = idx & 127;
        s_w[k * 65 + f] = Wm[idx];
    }
    __syncthreads();

    // agg = adj @ cur / norm  (thread does rows r and r+4 sharing cur loads)
    {
        int r = t >> 6, f = t & 63;
        const float* a0 = s_adj + r * 129;
        const float* a1 = s_adj + (r + 4) * 129;
        float acc0 = 0.0f, acc1 = 0.0f;
#pragma unroll 8
        for (int j = 0; j < NN; j++) {
            float c = s_cur[j * 64 + f];
            acc0 = fmaf(a0[j], c, acc0);
            acc1 = fmaf(a1[j], c, acc1);
        }
        s_agg[r * 64 + f] = acc0 / s_nm[r];
        s_agg[(r + 4) * 64 + f] = acc1 / s_nm[r + 4];
    }
    __syncthreads();

    // msg = relu([agg, ee] @ Wm^T)
    for (int o = t; o < 512; o += 256) {
        int r = o >> 6, f = o & 63;
        const float* ag = s_agg + r * 64;
        const float* ee = s_ee + r * 64;
        float acc = 0.0f;
#pragma unroll 8
        for (int k = 0; k < 64; k++) acc = fmaf(s_w[k * 65 + f], ag[k], acc);
#pragma unroll 8
        for (int k = 0; k < 64; k++) acc = fmaf(s_w[(64 + k) * 65 + f], ee[k], acc);
        s_msg[o] = fmaxf(acc, 0.0f);
    }
    __syncthreads();

    for (int idx = t; idx < 8192; idx += 256) {   // W_upd transposed into s_w
        int f = idx >> 7, k = idx & 127;
        s_w[k * 65 + f] = Wu[idx];
    }
    __syncthreads();

    // cur' = relu([cur, msg] @ Wu^T)
    for (int o = t; o < 512; o += 256) {
        int r = o >> 6, f = o & 63;
        const float* cu = s_cur + (r0 + r) * 64;
        const float* mg = s_msg + r * 64;
        float acc = 0.0f;
#pragma unroll 8
        for (int k = 0; k < 64; k++) acc = fmaf(s_w[k * 65 + f], cu[k], acc);
#pragma unroll 8
        for (int k = 0; k < 64; k++) acc = fmaf(s_w[(64 + k) * 65 + f], mg[k], acc);
        g_out[(b * NN + r0 + r) * FF + f] = fmaxf(acc, 0.0f);
    }
}

// ---------------- K4: pooling + readout precompute -------------------------
__global__ void k_pool(const float* __restrict__ Wp,
                       const float* __restrict__ Wr,
                       const float* __restrict__ br) {
    __shared__ float s_cur[8192];
    __shared__ float s_pool[64];
    __shared__ float s_rhp[64];
    int b = blockIdx.x, t = threadIdx.x;
    for (int idx = t; idx < 8192; idx += 256) s_cur[idx] = g_curB[b * 8192 + idx];
    __syncthreads();
    if (t < 64) {
        float s = 0.0f;
#pragma unroll 8
        for (int i = 0; i < NN; i++) s += s_cur[i * 64 + t];
        s_pool[t] = s * (1.0f / (float)NN);
    }
    __syncthreads();
    if (t < 64) {
        float acc = 0.0f;
#pragma unroll 8
        for (int g = 0; g < 64; g++) acc = fmaf(Wp[t * 64 + g], s_pool[g], acc);
        s_rhp[t] = fmaxf(acc, 0.0f);    // relu applied to h_pooled part of features
    }
    __syncthreads();
    if (t < 4) {
        float acc = br[t];
#pragma unroll 8
        for (int f = 0; f < 64; f++) acc = fmaf(Wr[t * 192 + f], s_rhp[f], acc);
        g_Abias[b * 4 + t] = acc;
    }
    // P[i][o], Q[i][o]
    for (int o = t; o < 1024; o += 256) {
        int i = o >> 3, c = o & 7;
        int oo = c & 3;
        const float* w = Wr + oo * 192 + ((c >= 4) ? 128 : 64);
        const float* cu = s_cur + i * 64;
        float acc = 0.0f;
#pragma unroll 8
        for (int f = 0; f < 64; f++) acc = fmaf(w[f], cu[f], acc);
        g_PQ[(b * NN + i) * 8 + c] = acc;
    }
}

// ---------------- K5: broadcast readout write ------------------------------
__global__ void k_out(float4* __restrict__ out) {
    int idx = blockIdx.x * blockDim.x + threadIdx.x;  // < B*N*N = 524288
    int j = idx & 127;
    int bi = idx >> 7;
    int b = idx >> 14;
    float4 A = *(const float4*)(g_Abias + b * 4);
    float4 P = *(const float4*)(g_PQ + bi * 8);
    float4 Q = *(const float4*)(g_PQ + (((b << 7) | j) * 8 + 4));
    float4 r;
    r.x = A.x + P.x + Q.x;
    r.y = A.y + P.y + Q.y;
    r.z = A.z + P.z + Q.z;
    r.w = A.w + P.w + Q.w;
    out[idx] = r;
}

// ---------------- host launcher --------------------------------------------
extern "C" void kernel_launch(void* const* d_in, const int* in_sizes, int n_in,
                              void* d_out, int out_size) {
    const float* obs    = (const float*)d_in[0];
    const float* W_init = (const float*)d_in[1];
    const float* W_ee   = (const float*)d_in[2];
    const float* W_ef   = (const float*)d_in[3];
    const float* W_msg  = (const float*)d_in[4];
    const float* W_upd  = (const float*)d_in[5];
    const float* W_pool = (const float*)d_in[6];
    const float* W_read = (const float*)d_in[7];
    const float* b_read = (const float*)d_in[8];

    cudaFuncSetAttribute(k_edge, cudaFuncAttributeMaxDynamicSharedMemorySize,
                         EDGE_SMEM_FLOATS * 4);
    cudaFuncSetAttribute(k_layer, cudaFuncAttributeMaxDynamicSharedMemorySize,
                         LAYER_SMEM_FLOATS * 4);

    k_norm<<<BB, NN>>>(obs);
    k_edge<<<BB * 8, 256, EDGE_SMEM_FLOATS * 4>>>(obs, W_init, W_ee, W_ef);
    for (int l = 0; l < 3; l++) {
        k_layer<<<BB * 16, 256, LAYER_SMEM_FLOATS * 4>>>(
            obs, W_msg + l * 64 * 128, W_upd + l * 64 * 128, l & 1);
    }
    k_pool<<<BB, 256>>>(W_pool, W_read, b_read);
    k_out<<<(BB * NN * NN) / 256, 256>>>((float4*)d_out);
}

// round 3
// speedup vs baseline: 1.1732x; 1.1732x over previous
#include <cuda_runtime.h>

#define BB 32
#define NN 128
#define DD 135
#define OBS 7
#define FF 64
#define ADJ_OFF 7

// ---------------- device global scratch (allocation-free) ----------------
__device__ float g_norm[BB * NN];
__device__ float g_ee[BB * NN * FF];
__device__ float g_curA[BB * NN * FF];
__device__ float g_curB[BB * NN * FF];
__device__ float g_PQ[BB * NN * 8];
__device__ float g_Abias[BB * 4];
__device__ float g_Wt[6 * 128 * 64];   // transposed W_msg/W_upd: [l*2+s][k][f]

// ---------------- K0: transpose layer weights once -------------------------
__global__ void k_wt(const float* __restrict__ Wm, const float* __restrict__ Wu) {
    int m = blockIdx.x;                     // 0..5
    const float* src = (m & 1) ? (Wu + (m >> 1) * 8192) : (Wm + (m >> 1) * 8192);
    float* dst = g_Wt + m * 8192;
    for (int i = threadIdx.x; i < 8192; i += 256) {
        int f = i >> 7, k = i & 127;        // src[f][k] row-major (64,128)
        dst[k * 64 + f] = src[i];
    }
}

// ---------------- K1: norm per column --------------------------------------
__global__ void k_norm(const float* __restrict__ obs) {
    int b = blockIdx.x, j = threadIdx.x;
    const float* o = obs + b * (NN * DD) + ADJ_OFF + j;
    int cnt = 0;
#pragma unroll 8
    for (int i = 0; i < NN; i++) cnt += (o[i * DD] != 0.0f) ? 1 : 0;
    g_norm[b * NN + j] = (cnt == 0) ? 1.0f : (float)cnt;
}

// ---------------- K2: edge stage + init embedding --------------------------
#define EDGE_SMEM_FLOATS (1024 + 512 + 512 + 64*65 + 8192 + 16*129 + 1024 + 128 + 256)
__global__ void k_edge(const float* __restrict__ obs,
                       const float* __restrict__ W_init,
                       const float* __restrict__ W_ee,
                       const float* __restrict__ W_ef) {
    extern __shared__ float sm[];
    float* s_nf   = sm;
    float* s_wee  = s_nf + 1024;
    float* s_wi   = s_wee + 512;
    float* s_weft = s_wi + 512;
    float* s_c    = s_weft + 64 * 65;
    float* s_adj  = s_c + 8192;
    float* s_es   = s_adj + 16 * 129;
    float* s_nm   = s_es + 1024;
    float* s_red  = s_nm + 128;

    int b = blockIdx.x >> 3;
    int r0 = (blockIdx.x & 7) << 4;
    int t = threadIdx.x;
    const float* ob = obs + b * NN * DD;

    for (int idx = t; idx < NN * OBS; idx += 256) {
        int j = idx / OBS, d = idx - j * OBS;
        s_nf[j * 8 + d] = ob[j * DD + d];
    }
    for (int idx = t; idx < 512; idx += 256)
        s_wee[idx] = (idx < 63 * 8) ? W_ee[idx] : 0.0f;
    for (int idx = t; idx < 512; idx += 256) {
        int f = idx >> 3, d = idx & 7;
        s_wi[idx] = (d < 7) ? W_init[f * 7 + d] : 0.0f;
    }
    for (int idx = t; idx < 4096; idx += 256) {
        int f = idx >> 6, k = idx & 63;
        s_weft[k * 65 + f] = W_ef[idx];
    }
    for (int idx = t; idx < 16 * NN; idx += 256) {
        int r = idx >> 7, j = idx & 127;
        s_adj[r * 129 + j] = ob[(r0 + r) * DD + ADJ_OFF + j];
    }
    for (int idx = t; idx < NN; idx += 256) s_nm[idx] = g_norm[b * NN + idx];
    float mx = 0.0f;
    for (int idx = t; idx < BB * NN; idx += 256) mx = fmaxf(mx, g_norm[idx]);
    s_red[t] = mx;
    __syncthreads();
    for (int s = 128; s > 0; s >>= 1) {
        if (t < s) s_red[t] = fmaxf(s_red[t], s_red[t + s]);
        __syncthreads();
    }
    float maxnorm = s_red[0];

    for (int idx = t; idx < NN * FF; idx += 256) {
        int j = idx >> 6, k = idx & 63;
        float c = 0.0f;
        if (k < 63) {
            const float* w = s_wee + k * 8;
            const float* nf = s_nf + j * 8;
#pragma unroll
            for (int d = 0; d < 7; d++) c = fmaf(w[d + 1], nf[d], c);
        }
        s_c[idx] = c;
    }
    for (int idx = t; idx < 16 * FF; idx += 256) {
        int r = idx >> 6, f = idx & 63;
        const float* w = s_wi + f * 8;
        const float* nf = s_nf + (r0 + r) * 8;
        float e = 0.0f;
#pragma unroll
        for (int d = 0; d < 7; d++) e = fmaf(w[d], nf[d], e);
        g_curA[(b * NN + r0 + r) * FF + f] = fmaxf(e, 0.0f);
    }
    __syncthreads();

    {
        int r = t >> 4, g = t & 15;
        int f0 = g << 2;
        float4 w0;
        w0.x = s_wee[(f0 + 0) * 8];
        w0.y = s_wee[(f0 + 1) * 8];
        w0.z = s_wee[(f0 + 2) * 8];
        w0.w = s_wee[(f0 + 3) * 8];
        float4 acc = make_float4(0.f, 0.f, 0.f, 0.f);
        const float* arow = s_adj + r * 129;
        for (int j = 0; j < NN; j++) {
            float a = arow[j];
            if (a != 0.0f) {
                float4 c = *(const float4*)(s_c + j * 64 + f0);
                acc.x += fmaxf(fmaf(a, w0.x, c.x), 0.0f);
                acc.y += fmaxf(fmaf(a, w0.y, c.y), 0.0f);
                acc.z += fmaxf(fmaf(a, w0.z, c.z), 0.0f);
                acc.w += fmaxf(fmaf(a, w0.w, c.w), 0.0f);
            }
        }
        float nrm = s_nm[r0 + r];
        float inv = 1.0f / nrm;
        float* es = s_es + r * 64 + f0;
        es[0] = acc.x * inv;
        es[1] = acc.y * inv;
        es[2] = acc.z * inv;
        es[3] = (g == 15) ? (nrm / maxnorm) : acc.w * inv;
    }
    __syncthreads();

    for (int idx = t; idx < 16 * FF; idx += 256) {
        int r = idx >> 6, f = idx & 63;
        const float* e = s_es + r * 64;
        float acc = 0.0f;
#pragma unroll 16
        for (int k = 0; k < 64; k++) acc = fmaf(s_weft[k * 65 + f], e[k], acc);
        g_ee[(b * NN + r0 + r) * FF + f] = fmaxf(acc, 0.0f);
    }
}

// ---------------- K3: MPNN layer (register-tiled FFMA2) --------------------
// strides (floats): cur/w = 72, dup buffers = 34
#define SCW 72
#define SDP 34
#define L_SMEM_BYTES ((128*SCW + 128*SCW + 128*SDP + 128*SDP + 16) * 4)

// one GEMM-ish stage: out[4r][4f] = sum over K=128 (K-split 4 + shfl reduce)
//  dup operand:  s[k][2r] == s[k][2r+1]  (stride SDP floats)
//  pair operand: s[k][f0..f0+3]          (stride SCW floats)
__device__ __forceinline__ void mma_stage(unsigned dup_addr, unsigned pair_addr,
                                          float res[4][4]) {
    unsigned long long acc[4][2];
#pragma unroll
    for (int i = 0; i < 4; i++) { acc[i][0] = 0ull; acc[i][1] = 0ull; }
#pragma unroll 8
    for (int it = 0; it < 32; it++) {
        unsigned long long a0, a1, a2, a3, c0, c1;
        asm volatile("ld.shared.b64 %0, [%1];" : "=l"(a0) : "r"(dup_addr));
        asm volatile("ld.shared.b64 %0, [%1];" : "=l"(a1) : "r"(dup_addr + 8));
        asm volatile("ld.shared.b64 %0, [%1];" : "=l"(a2) : "r"(dup_addr + 16));
        asm volatile("ld.shared.b64 %0, [%1];" : "=l"(a3) : "r"(dup_addr + 24));
        asm volatile("ld.shared.v2.b64 {%0,%1}, [%2];"
                     : "=l"(c0), "=l"(c1) : "r"(pair_addr));
        asm volatile("fma.rn.f32x2 %0, %1, %2, %0;" : "+l"(acc[0][0]) : "l"(a0), "l"(c0));
        asm volatile("fma.rn.f32x2 %0, %1, %2, %0;" : "+l"(acc[0][1]) : "l"(a0), "l"(c1));
        asm volatile("fma.rn.f32x2 %0, %1, %2, %0;" : "+l"(acc[1][0]) : "l"(a1), "l"(c0));
        asm volatile("fma.rn.f32x2 %0, %1, %2, %0;" : "+l"(acc[1][1]) : "l"(a1), "l"(c1));
        asm volatile("fma.rn.f32x2 %0, %1, %2, %0;" : "+l"(acc[2][0]) : "l"(a2), "l"(c0));
        asm volatile("fma.rn.f32x2 %0, %1, %2, %0;" : "+l"(acc[2][1]) : "l"(a2), "l"(c1));
        asm volatile("fma.rn.f32x2 %0, %1, %2, %0;" : "+l"(acc[3][0]) : "l"(a3), "l"(c0));
        asm volatile("fma.rn.f32x2 %0, %1, %2, %0;" : "+l"(acc[3][1]) : "l"(a3), "l"(c1));
        dup_addr += 4 * SDP * 4;
        pair_addr += 4 * SCW * 4;
    }
#pragma unroll
    for (int ri = 0; ri < 4; ri++)
#pragma unroll
        for (int fp = 0; fp < 2; fp++) {
            float lo, hi;
            asm("mov.b64 {%0,%1}, %2;" : "=f"(lo), "=f"(hi) : "l"(acc[ri][fp]));
            lo += __shfl_xor_sync(0xffffffffu, lo, 1);
            lo += __shfl_xor_sync(0xffffffffu, lo, 2);
            hi += __shfl_xor_sync(0xffffffffu, hi, 1);
            hi += __shfl_xor_sync(0xffffffffu, hi, 2);
            res[ri][fp * 2] = lo;
            res[ri][fp * 2 + 1] = hi;
        }
}

// grid = 32 batches * 8 chunks (16 rows), 256 threads
__global__ __launch_bounds__(256, 2)
void k_layer(const float* __restrict__ obs, int layer, int flip) {
    extern __shared__ float sm[];
    float* s_cur = sm;                      // [128][72] full-batch cur
    float* s_w   = sm + 128 * SCW;          // [128][72] transposed weights
    float* s_ad  = s_w + 128 * SCW;         // [128][34] adj dup-transposed [j][2r]
    float* s_xd  = s_ad + 128 * SDP;        // [128][34] concat-input dup-transposed
    float* s_nm  = s_xd + 128 * SDP;        // [16]

    const float* g_in = flip ? g_curB : g_curA;
    float* g_out      = flip ? g_curA : g_curB;
    const float* Wm = g_Wt + (layer * 2) * 8192;
    const float* Wu = g_Wt + (layer * 2 + 1) * 8192;

    int t = threadIdx.x;
    int b = blockIdx.x >> 3;
    int r0 = (blockIdx.x & 7) << 4;
    const float* ob = obs + b * NN * DD;

    // fill cur (full batch), W_msg, adj (dup-transposed), ee (dup-transposed)
    {
        const float4* gc = (const float4*)(g_in + b * 8192);
        for (int i = t; i < 2048; i += 256) {
            float4 v = gc[i];
            *(float4*)&s_cur[(i >> 4) * SCW + ((i & 15) << 2)] = v;
        }
        const float4* gw = (const float4*)Wm;
        for (int i = t; i < 2048; i += 256) {
            float4 v = gw[i];
            *(float4*)&s_w[(i >> 4) * SCW + ((i & 15) << 2)] = v;
        }
        for (int i = t; i < 2048; i += 256) {
            int r = i >> 7, j = i & 127;
            float a = ob[(r0 + r) * DD + ADJ_OFF + j];
            s_ad[j * SDP + 2 * r] = a;
            s_ad[j * SDP + 2 * r + 1] = a;
        }
        for (int i = t; i < 1024; i += 256) {
            int r = i >> 6, f = i & 63;
            float e = g_ee[(b * NN + r0 + r) * FF + f];
            s_xd[(64 + f) * SDP + 2 * r] = e;
            s_xd[(64 + f) * SDP + 2 * r + 1] = e;
        }
        if (t < 16) s_nm[t] = g_norm[b * NN + r0 + t];
    }
    __syncthreads();

    int kk = t & 3, rt = (t >> 2) & 3, ft = t >> 4;
    unsigned sbase = (unsigned)__cvta_generic_to_shared(sm);
    unsigned CU = sbase;
    unsigned WB = sbase + 128 * SCW * 4;
    unsigned AD = WB + 128 * SCW * 4;
    unsigned XD = AD + 128 * SDP * 4;
    unsigned dup0 = (unsigned)(kk * SDP + 8 * rt) * 4;
    unsigned pr0  = (unsigned)(kk * SCW + ft * 4) * 4;

    float res[4][4];

    // stage 1: agg = adj @ cur / norm  -> s_xd[0..63]
    mma_stage(AD + dup0, CU + pr0, res);
    if (kk == 0) {
#pragma unroll
        for (int ri = 0; ri < 4; ri++) {
            int r = rt * 4 + ri;
            float inv = 1.0f / s_nm[r];
#pragma unroll
            for (int fj = 0; fj < 4; fj++) {
                float v = res[ri][fj] * inv;
                int f = ft * 4 + fj;
                s_xd[f * SDP + 2 * r] = v;
                s_xd[f * SDP + 2 * r + 1] = v;
            }
        }
    }
    __syncthreads();

    // stage 2: msg = relu([agg, ee] @ Wm^T)
    mma_stage(XD + dup0, WB + pr0, res);
    __syncthreads();
    if (kk == 0) {
#pragma unroll
        for (int ri = 0; ri < 4; ri++) {
            int r = rt * 4 + ri;
#pragma unroll
            for (int fj = 0; fj < 4; fj++) {
                float v = fmaxf(res[ri][fj], 0.0f);
                int f = ft * 4 + fj;
                s_xd[(64 + f) * SDP + 2 * r] = v;
                s_xd[(64 + f) * SDP + 2 * r + 1] = v;
            }
        }
    }
    // copy own cur rows into s_xd[0..63] and reload weights (Wu)
    for (int i = t; i < 1024; i += 256) {
        int r = i >> 6, f = i & 63;
        float c = s_cur[(r0 + r) * SCW + f];
        s_xd[f * SDP + 2 * r] = c;
        s_xd[f * SDP + 2 * r + 1] = c;
    }
    {
        const float4* gw2 = (const float4*)Wu;
        for (int i = t; i < 2048; i += 256) {
            float4 v = gw2[i];
            *(float4*)&s_w[(i >> 4) * SCW + ((i & 15) << 2)] = v;
        }
    }
    __syncthreads();

    // stage 3: cur' = relu([cur, msg] @ Wu^T) -> global
    mma_stage(XD + dup0, WB + pr0, res);
    if (kk == 0) {
#pragma unroll
        for (int ri = 0; ri < 4; ri++) {
            int rg = (b * NN + r0 + rt * 4 + ri) * FF + ft * 4;
            float4 o;
            o.x = fmaxf(res[ri][0], 0.0f);
            o.y = fmaxf(res[ri][1], 0.0f);
            o.z = fmaxf(res[ri][2], 0.0f);
            o.w = fmaxf(res[ri][3], 0.0f);
            *(float4*)&g_out[rg] = o;
        }
    }
}

// ---------------- K4: pooling + readout precompute -------------------------
__global__ void k_pool(const float* __restrict__ Wp,
                       const float* __restrict__ Wr,
                       const float* __restrict__ br) {
    __shared__ float s_cur[8192];
    __shared__ float s_pool[64];
    __shared__ float s_rhp[64];
    int b = blockIdx.x, t = threadIdx.x;
    for (int idx = t; idx < 8192; idx += 256) s_cur[idx] = g_curB[b * 8192 + idx];
    __syncthreads();
    if (t < 64) {
        float s = 0.0f;
#pragma unroll 8
        for (int i = 0; i < NN; i++) s += s_cur[i * 64 + t];
        s_pool[t] = s * (1.0f / (float)NN);
    }
    __syncthreads();
    if (t < 64) {
        float acc = 0.0f;
#pragma unroll 8
        for (int g = 0; g < 64; g++) acc = fmaf(Wp[t * 64 + g], s_pool[g], acc);
        s_rhp[t] = fmaxf(acc, 0.0f);
    }
    __syncthreads();
    if (t < 4) {
        float acc = br[t];
#pragma unroll 8
        for (int f = 0; f < 64; f++) acc = fmaf(Wr[t * 192 + f], s_rhp[f], acc);
        g_Abias[b * 4 + t] = acc;
    }
    for (int o = t; o < 1024; o += 256) {
        int i = o >> 3, c = o & 7;
        int oo = c & 3;
        const float* w = Wr + oo * 192 + ((c >= 4) ? 128 : 64);
        const float* cu = s_cur + i * 64;
        float acc = 0.0f;
#pragma unroll 8
        for (int f = 0; f < 64; f++) acc = fmaf(w[f], cu[f], acc);
        g_PQ[(b * NN + i) * 8 + c] = acc;
    }
}

// ---------------- K5: broadcast readout write ------------------------------
__global__ void k_out(float4* __restrict__ out) {
    int idx = blockIdx.x * blockDim.x + threadIdx.x;
    int j = idx & 127;
    int bi = idx >> 7;
    int b = idx >> 14;
    float4 A = *(const float4*)(g_Abias + b * 4);
    float4 P = *(const float4*)(g_PQ + bi * 8);
    float4 Q = *(const float4*)(g_PQ + (((b << 7) | j) * 8 + 4));
    float4 r;
    r.x = A.x + P.x + Q.x;
    r.y = A.y + P.y + Q.y;
    r.z = A.z + P.z + Q.z;
    r.w = A.w + P.w + Q.w;
    out[idx] = r;
}

// ---------------- host launcher --------------------------------------------
extern "C" void kernel_launch(void* const* d_in, const int* in_sizes, int n_in,
                              void* d_out, int out_size) {
    const float* obs    = (const float*)d_in[0];
    const float* W_init = (const float*)d_in[1];
    const float* W_ee   = (const float*)d_in[2];
    const float* W_ef   = (const float*)d_in[3];
    const float* W_msg  = (const float*)d_in[4];
    const float* W_upd  = (const float*)d_in[5];
    const float* W_pool = (const float*)d_in[6];
    const float* W_read = (const float*)d_in[7];
    const float* b_read = (const float*)d_in[8];

    cudaFuncSetAttribute(k_edge, cudaFuncAttributeMaxDynamicSharedMemorySize,
                         EDGE_SMEM_FLOATS * 4);
    cudaFuncSetAttribute(k_layer, cudaFuncAttributeMaxDynamicSharedMemorySize,
                         L_SMEM_BYTES);

    k_wt<<<6, 256>>>(W_msg, W_upd);
    k_norm<<<BB, NN>>>(obs);
    k_edge<<<BB * 8, 256, EDGE_SMEM_FLOATS * 4>>>(obs, W_init, W_ee, W_ef);
    for (int l = 0; l < 3; l++) {
        k_layer<<<BB * 8, 256, L_SMEM_BYTES>>>(obs, l, l & 1);
    }
    k_pool<<<BB, 256>>>(W_pool, W_read, b_read);
    k_out<<<(BB * NN * NN) / 256, 256>>>((float4*)d_out);
}